// round 17
// baseline (speedup 1.0000x reference)
#include <cuda_runtime.h>
#include <cstdint>

// SVConvTranspose2d, round 17: barrier-free warp-private cp.async ring.
//
// R13 (champion, 71.7us, DRAM 75.6%) is pinned at 5 weight lines in flight
// per warp (register-batched; acc[4][8] leaves no room for more) =
// 17.9 KB/SM ~= the latency-BW product. cp.async breaks that: each thread
// streams ITS OWN 16B of iteration itr+2's weight rows into a 3-stage smem
// ring and LDS-reads back its own bytes -> producer==consumer per thread,
// so NO barriers anywhere in the loop. wait_group 2 keeps 2 stages
// (10 unique lines/warp = 35.8 KB/SM) outstanding at all times.
//
// x:      (4, 16, 128, 128) f32        -- 4 MB, L2-hot
// weight: (16, 16, 5, 5, 128, 128) f32 -- 419 MB, read EXACTLY once
//                                         (cp.async.cg: L1-bypass stream)
// bias:   (1, 16, 1, 1) f32
// out:    (4, 16, 128, 128) f32
//
// out[n,o,oh,ow] = bias[o] + sum wt[i,o,kh,kw,h,w] * x[n,i,h,w],
//   h = oh+2-kh (gather), ow = w+kw-2 (scatter into acc window).
//
// Thread = (q:32 quads, o2:2 outs, ih:2 i-slices of 8); all 4 batches
// (weights unique per thread -- the property every failed round violated).
// acc[4][8] window over out positions [4q-2,4q+6): tap (kw,j) -> j+kw.
// Iteration itr over valid (kh,ii): issue itr+2 (5 cp.async/thread),
// commit, wait_group 2, LDS.128 x5, 2x(2 x-quads + 40 FMA).
// Grid = 1024 blocks x 128 thr, 7 blocks/SM -> SINGLE wave (1036 >= 1024).
// Smem: 30 KB ring (static), aliased as the 4 KB reduce buffer afterwards.

#define H_  128
#define W_  128
#define HW  16384
#define RS  3                       // ring stages

__device__ __forceinline__ void cp_async16(uint32_t saddr, const void* gptr) {
    asm volatile("cp.async.cg.shared.global [%0], [%1], 16;\n"
                 :: "r"(saddr), "l"(gptr) : "memory");
}
__device__ __forceinline__ void cp_commit() {
    asm volatile("cp.async.commit_group;\n" ::: "memory");
}
__device__ __forceinline__ void cp_wait2() {
    asm volatile("cp.async.wait_group 2;\n" ::: "memory");
}

__global__ __launch_bounds__(128, 7)
void svct_kernel(const float* __restrict__ x,
                 const float* __restrict__ wt,
                 const float* __restrict__ bias,
                 float* __restrict__ out)
{
    // [stage][warp][kw][lane] float4 = 3*4*5*32*16 = 30 KB.
    // Re-used as the reduce buffer after the mainloop (barrier in between).
    __shared__ float4 wring[RS][4][5][32];

    const int t   = threadIdx.x;
    const int q   = t & 31;              // quad index in row == lane
    const int o2  = (t >> 5) & 1;        // which of the 2 outs
    const int ih  = (t >> 6) & 1;        // i-slice of 8
    const int wid = t >> 5;              // warp id 0..3
    const int oh  = blockIdx.x >> 3;     // output row
    const int og  = blockIdx.x & 7;      // o-pair
    const int oc  = og * 2 + o2;         // output channel
    const int ibase = ih * 8;

    // valid kh range so every streamed address is in-bounds
    const int kh_lo = (oh > 125) ? (oh - 125) : 0;
    const int kh_hi = (oh < 2) ? (oh + 2) : 4;
    const int nit   = (kh_hi - kh_lo + 1) * 8;   // 24..40 iterations

    const uint32_t sbase =
        (uint32_t)__cvta_generic_to_shared(&wring[0][wid][0][q]);
    const uint32_t stage_stride = 4u * 5u * 32u * 16u;   // 10240 B
    const uint32_t kw_stride    = 32u * 16u;             // 512 B

    float acc[4][8];                     // [n][window k]
    #pragma unroll
    for (int n = 0; n < 4; n++)
        #pragma unroll
        for (int k = 0; k < 8; k++)
            acc[n][k] = 0.0f;

    // issue stage s = linear iteration index (kh = kh_lo + s/8, ii = s%8)
    auto issue = [&](int s) {
        const int kh2 = kh_lo + (s >> 3);
        const int i2  = ibase + (s & 7);
        const int h2  = oh + 2 - kh2;
        const float* wr = wt + ((long)((i2 * 16 + oc) * 5 + kh2) * 5) * HW
                             + (long)h2 * W_;
        const uint32_t sb = sbase + (uint32_t)(s % RS) * stage_stride;
        #pragma unroll
        for (int kw = 0; kw < 5; kw++)
            cp_async16(sb + (uint32_t)kw * kw_stride,
                       (const float4*)(wr + (long)kw * HW) + q);
    };

    // prologue: nit >= 24, so stages 0 and 1 always exist
    issue(0); cp_commit();
    issue(1); cp_commit();

    #pragma unroll 1
    for (int itr = 0; itr < nit; itr++) {
        // keep 2 stages in flight; commit even when empty to keep counts
        if (itr + 2 < nit) issue(itr + 2);
        cp_commit();
        cp_wait2();                 // stage itr complete; itr+1, itr+2 flying

        // ---- consume stage itr: each thread reads back its own bytes
        const int kh = kh_lo + (itr >> 3);
        const int i  = ibase + (itr & 7);
        const int h  = oh + 2 - kh;

        const float4* sl = &wring[itr % RS][wid][0][q];
        float4 w4[5];
        #pragma unroll
        for (int kw = 0; kw < 5; kw++)
            w4[kw] = sl[kw * 32];

        #pragma unroll
        for (int half = 0; half < 2; half++) {
            float4 xq[2];
            #pragma unroll
            for (int m = 0; m < 2; m++)
                xq[m] = __ldg((const float4*)x
                              + (((half * 2 + m) * 16 + i) * H_ + h) * 32 + q);

            #pragma unroll
            for (int kw = 0; kw < 5; kw++) {
                const float wv[4] = {w4[kw].x, w4[kw].y, w4[kw].z, w4[kw].w};
                #pragma unroll
                for (int m = 0; m < 2; m++) {
                    const int n = half * 2 + m;
                    const float xv[4] = {xq[m].x, xq[m].y, xq[m].z, xq[m].w};
                    #pragma unroll
                    for (int j = 0; j < 4; j++)
                        acc[n][j + kw] = fmaf(wv[j], xv[j], acc[n][j + kw]);
                }
            }
        }
    }

    // ---- epilogue: alias the ring as the reduce buffer
    __syncthreads();                       // all warps done with wring
    float (*red)[4][2][W_] = (float (*)[4][2][W_])wring;  // [o2][n][ih][w]

    const bool q0  = (q == 0);
    const bool q31 = (q == 31);
    #pragma unroll
    for (int n = 0; n < 4; n++) {
        float up6 = __shfl_up_sync(0xffffffffu, acc[n][6], 1);
        float up7 = __shfl_up_sync(0xffffffffu, acc[n][7], 1);
        float dn0 = __shfl_down_sync(0xffffffffu, acc[n][0], 1);
        float dn1 = __shfl_down_sync(0xffffffffu, acc[n][1], 1);
        if (q0)  { up6 = 0.0f; up7 = 0.0f; }
        if (q31) { dn0 = 0.0f; dn1 = 0.0f; }
        *(float4*)&red[o2][n][ih][4 * q] =
            make_float4(acc[n][2] + up6, acc[n][3] + up7,
                        acc[n][4] + dn0, acc[n][5] + dn1);
    }
    __syncthreads();

    // 128 threads write 256 float4 outputs: 2 per thread
    #pragma unroll
    for (int rep = 0; rep < 2; rep++) {
        const int idx = t + rep * 128;        // (o2w:2)(nw:4)(qw:32)
        const int o2w = idx >> 7;
        const int nw  = (idx >> 5) & 3;
        const int qw  = idx & 31;
        const int ocw = og * 2 + o2w;

        float4 s0 = *(const float4*)&red[o2w][nw][0][4 * qw];
        float4 s1 = *(const float4*)&red[o2w][nw][1][4 * qw];

        const float b = __ldg(bias + ocw);
        float4 r;
        r.x = s0.x + s1.x + b;
        r.y = s0.y + s1.y + b;
        r.z = s0.z + s1.z + b;
        r.w = s0.w + s1.w + b;

        ((float4*)out)[((nw * 16 + ocw) * H_ + oh) * 32 + qw] = r;
    }
}

extern "C" void kernel_launch(void* const* d_in, const int* in_sizes, int n_in,
                              void* d_out, int out_size)
{
    const float* x    = (const float*)d_in[0];
    const float* wt   = (const float*)d_in[1];
    const float* bias = (const float*)d_in[2];
    float*       out  = (float*)d_out;

    svct_kernel<<<1024, 128>>>(x, wt, bias, out);
}